// round 1
// baseline (speedup 1.0000x reference)
#include <cuda_runtime.h>

#define IMGSZ 64
#define DSTEPS 64
#define NB 4
#define DSH 61
#define H1 128
#define NPIX (IMGSZ * IMGSZ)

// scratch (no allocations allowed)
__device__ float g_hb[NB][H1];     // per-batch hidden bias (b1 + z_shape part + B part)
__device__ float g_cst[NB][12];    // M[9], s_inv, bb_depth

// ---------------------------------------------------------------------------
// Precompute per-batch constants: folded matrix M = s_obj*R_obj*K_inv,
// B-part folded into hidden bias, s_inv, bb_depth.
// grid = NB blocks, 128 threads (one per hidden unit)
// ---------------------------------------------------------------------------
__global__ void precomp_kernel(const float* __restrict__ z_shape,
                               const float* __restrict__ z_extr,
                               const float* __restrict__ W1,
                               const float* __restrict__ b1) {
    int b = blockIdx.x;
    int j = threadIdx.x;  // 0..127

    float scale = z_extr[b * 5 + 0];
    float tox   = z_extr[b * 5 + 1];
    float toy   = z_extr[b * 5 + 2];
    float toz   = z_extr[b * 5 + 3];
    float alpha = z_extr[b * 5 + 4];

    float s_obj = 1.0f / scale;          // reference: s_obj = 1/z_extr[:,0]
    float s_inv = 1.0f / s_obj;          // reference: s_inv = 1/s_obj
    float ang = 3.14159265358979323846f * alpha;  // f32 pi * alpha
    float ca = cosf(ang), sa = sinf(ang);

    // R_obj = Z-rotation: [[c,-s,0],[s,c,0],[0,0,1]]
    // K_inv analytic: [[1/f,0,-c/f],[0,1/f,-c/f],[0,0,1]], f=70, c=31.5
    const float f = 70.0f;
    const float cc = 31.5f;
    float invf = 1.0f / f;
    float Ki02 = -cc * invf;

    // M = s_obj * R_obj @ K_inv  (row 2 of R_obj is [0,0,1])
    float M00 = s_obj * ( ca * invf);
    float M01 = s_obj * (-sa * invf);
    float M02 = s_obj * ( ca * Ki02 + (-sa) * Ki02);
    float M10 = s_obj * ( sa * invf);
    float M11 = s_obj * ( ca * invf);
    float M12 = s_obj * ( sa * Ki02 + ( ca) * Ki02);
    float M22 = s_obj;                       // (0,0,1)@Kinv col2 = 1

    // B = s_obj * R_obj @ (-t - t_obj), t = (0,0,2.5)
    float wx = -tox, wy = -toy, wz = -2.5f - toz;
    float Bx = s_obj * (ca * wx + (-sa) * wy);
    float By = s_obj * (sa * wx + ( ca) * wy);
    float Bz = s_obj * wz;

    // bb_depth: mean camera-z of 9 bbox points.
    // z-comp of R_obj_inv @ (s_inv*corner) is s_inv*corner_z (rotation about z).
    const float cz[9] = {1.f,-1.f,1.f,-1.f,1.f,-1.f,1.f,-1.f,0.f};
    float acc = 0.f;
    #pragma unroll
    for (int a = 0; a < 9; a++) acc += s_inv * cz[a] + toz + 2.5f;
    float bb = acc / 9.0f;

    // hidden bias: b1 + B·W1[0:3] + z_shape·W1[3:]
    float h = b1[j];
    h += Bx * W1[0 * H1 + j];
    h += By * W1[1 * H1 + j];
    h += Bz * W1[2 * H1 + j];
    #pragma unroll 4
    for (int ff = 0; ff < DSH; ff++)
        h += z_shape[b * DSH + ff] * W1[(3 + ff) * H1 + j];
    g_hb[b][j] = h;

    if (j == 0) {
        g_cst[b][0] = M00; g_cst[b][1] = M01; g_cst[b][2] = M02;
        g_cst[b][3] = M10; g_cst[b][4] = M11; g_cst[b][5] = M12;
        g_cst[b][6] = 0.f; g_cst[b][7] = 0.f; g_cst[b][8] = M22;
        g_cst[b][9] = s_inv; g_cst[b][10] = bb;
    }
}

// ---------------------------------------------------------------------------
// Main render: 1 warp per ray (pixel,batch). Lane l owns depths 2l, 2l+1.
// grid = 16384/8 = 2048 blocks of 256 threads (8 warps). All warps of a
// block belong to the same batch (4096 rays/batch, 8 | 4096).
// ---------------------------------------------------------------------------
__global__ __launch_bounds__(256) void render_kernel(
    const float* __restrict__ W1, const float* __restrict__ W2,
    const float* __restrict__ b2, float* __restrict__ out) {

    __shared__ float s_hb[H1];
    __shared__ float s_w2[H1];
    __shared__ float s_cst[12];
    __shared__ float s_g[8][H1];

    int tid  = threadIdx.x;
    int warp = tid >> 5;
    int lane = tid & 31;
    int ray0 = blockIdx.x * 8;
    int b    = ray0 >> 12;   // 4096 rays per batch

    if (tid < H1) s_hb[tid] = g_hb[b][tid];
    else          s_w2[tid - H1] = W2[tid - H1];
    if (tid < 12) s_cst[tid] = g_cst[b][tid];
    __syncthreads();

    int ray = ray0 + warp;
    int p   = ray & (NPIX - 1);
    float x = (float)(p & 63);   // meshgrid 'xy': x fastest
    float y = (float)(p >> 6);

    float Ax = s_cst[0] * x + s_cst[1] * y + s_cst[2];
    float Ay = s_cst[3] * x + s_cst[4] * y + s_cst[5];
    float Az = s_cst[8];
    float s_inv = s_cst[9], bb = s_cst[10];

    // per-ray gradient vector g[j] = A · W1[0:3,j]  -> shared
    #pragma unroll
    for (int k = 0; k < 4; k++) {
        int j = lane + 32 * k;
        s_g[warp][j] = Ax * W1[j] + Ay * W1[H1 + j] + Az * W1[2 * H1 + j];
    }
    __syncwarp();

    const float zstep = 2.0f / 63.0f;
    int d0 = 2 * lane;
    float Z0 = fmaf(-1.0f + (float)(d0    ) * zstep, s_inv, bb);
    float Z1 = fmaf(-1.0f + (float)(d0 + 1) * zstep, s_inv, bb);
    float Z2 = fmaf(-1.0f + (float)(d0 + 2) * zstep, s_inv, bb);

    float acc0 = 0.f, acc1 = 0.f;
    #pragma unroll
    for (int j = 0; j < H1; j += 4) {
        float4 gv = *(const float4*)&s_g[warp][j];
        float4 hv = *(const float4*)&s_hb[j];
        float4 wv = *(const float4*)&s_w2[j];
        float t;
        t = fmaf(Z0, gv.x, hv.x); acc0 = fmaf(fmaxf(t, 0.f), wv.x, acc0);
        t = fmaf(Z1, gv.x, hv.x); acc1 = fmaf(fmaxf(t, 0.f), wv.x, acc1);
        t = fmaf(Z0, gv.y, hv.y); acc0 = fmaf(fmaxf(t, 0.f), wv.y, acc0);
        t = fmaf(Z1, gv.y, hv.y); acc1 = fmaf(fmaxf(t, 0.f), wv.y, acc1);
        t = fmaf(Z0, gv.z, hv.z); acc0 = fmaf(fmaxf(t, 0.f), wv.z, acc0);
        t = fmaf(Z1, gv.z, hv.z); acc1 = fmaf(fmaxf(t, 0.f), wv.z, acc1);
        t = fmaf(Z0, gv.w, hv.w); acc0 = fmaf(fmaxf(t, 0.f), wv.w, acc0);
        t = fmaf(Z1, gv.w, hv.w); acc1 = fmaf(fmaxf(t, 0.f), wv.w, acc1);
    }

    float b2v = b2[0];
    float sdf0 = tanhf(acc0 + b2v);  // depth 2*lane
    float sdf1 = tanhf(acc1 + b2v);  // depth 2*lane+1

    // sdf at depth 2*lane+2 lives in lane+1's sdf0
    float nxt = __shfl_down_sync(0xffffffffu, sdf0, 1);

    bool cra = (sdf0 > 0.f) && (sdf1 <= 0.f);                   // pair (2l, 2l+1)
    bool crb = (lane < 31) && (sdf1 > 0.f) && (nxt <= 0.f);     // pair (2l+1, 2l+2)

    float s1 = (cra ? sdf0 : 0.f) + (crb ? sdf1 : 0.f);
    float s2 = (cra ? sdf1 : 0.f) + (crb ? nxt  : 0.f);
    float d1 = fminf(cra ? Z0 : 100.f, crb ? Z1 : 100.f);
    float d2 = fminf(cra ? Z1 : 100.f, crb ? Z2 : 100.f);
    float occ = (cra || crb) ? 1.f : 0.f;

    #pragma unroll
    for (int o = 16; o; o >>= 1) {
        s1 += __shfl_xor_sync(0xffffffffu, s1, o);
        s2 += __shfl_xor_sync(0xffffffffu, s2, o);
        d1  = fminf(d1, __shfl_xor_sync(0xffffffffu, d1, o));
        d2  = fminf(d2, __shfl_xor_sync(0xffffffffu, d2, o));
        occ = fmaxf(occ, __shfl_xor_sync(0xffffffffu, occ, o));
    }

    if (lane == 0) {
        float depth = occ * (d1 - s1 / (s2 - s1 - 1e-6f) * (d2 - d1));
        out[ray] = depth;                 // depth_pred (BS,64,64,1)
        out[NB * NPIX + ray] = occ;       // occ        (BS,64,64,1)
    }
}

extern "C" void kernel_launch(void* const* d_in, const int* in_sizes, int n_in,
                              void* d_out, int out_size) {
    const float* z_shape = (const float*)d_in[0];  // (4,61)
    const float* z_extr  = (const float*)d_in[1];  // (4,5)
    const float* W1      = (const float*)d_in[2];  // (64,128)
    const float* b1      = (const float*)d_in[3];  // (128,)
    const float* W2      = (const float*)d_in[4];  // (128,1)
    const float* b2      = (const float*)d_in[5];  // (1,)
    float* out = (float*)d_out;

    precomp_kernel<<<NB, H1>>>(z_shape, z_extr, W1, b1);
    render_kernel<<<(NB * NPIX) / 8, 256>>>(W1, W2, b2, out);
}